// round 2
// baseline (speedup 1.0000x reference)
#include <cuda_runtime.h>

#define T_STEPS 512
#define IN      9
#define HID     56
#define G4      224     // 4*HID
#define BB      14      // batches per CTA
#define NT      256     // threads per CTA

// overflow-safe fast tanh: exp argument always <= 0
__device__ __forceinline__ float tanh_fast(float v) {
    float e = __expf(-2.0f * fabsf(v));
    float t = __fdividef(1.0f - e, 1.0f + e);
    return copysignf(t, v);
}

__device__ __forceinline__ float sigmoid_fast(float v) {
    return __fdividef(1.0f, 1.0f + __expf(-v));
}

__global__ void __launch_bounds__(NT, 1)
lstm_fused_kernel(const float* __restrict__ x,
                  const float* __restrict__ w_ih0, const float* __restrict__ w_hh0,
                  const float* __restrict__ b_ih0, const float* __restrict__ b_hh0,
                  const float* __restrict__ w_ih1, const float* __restrict__ w_hh1,
                  const float* __restrict__ b_ih1, const float* __restrict__ b_hh1,
                  const float* __restrict__ fc1_w, const float* __restrict__ fc1_b,
                  const float* __restrict__ fc2_w, const float* __restrict__ fc2_b,
                  float* __restrict__ out, int batch_total)
{
    __shared__ float xs[BB][IN];
    __shared__ __align__(16) float h0s[BB][HID];
    __shared__ __align__(16) float h1s[BB][HID];
    __shared__ float gsh[BB][G4];

    const int tid = threadIdx.x;
    const int b0  = blockIdx.x * BB;
    const int nb  = min(BB, batch_total - b0);   // uniform across block

    // ---- per-gate weights in registers (threads 0..223) ----
    float wx[IN], w0[HID], wi1[HID], w1[HID];
    float bias0 = 0.0f, bias1 = 0.0f;
    const int g = tid;
    if (tid < G4) {
        #pragma unroll
        for (int j = 0; j < IN; j++)  wx[j]  = w_ih0[g * IN + j];
        #pragma unroll
        for (int k = 0; k < HID; k++) w0[k]  = w_hh0[g * HID + k];
        #pragma unroll
        for (int k = 0; k < HID; k++) wi1[k] = w_ih1[g * HID + k];
        #pragma unroll
        for (int k = 0; k < HID; k++) w1[k]  = w_hh1[g * HID + k];
        bias0 = b_ih0[g] + b_hh0[g];
        bias1 = b_ih1[g] + b_hh1[g];
    }

    // ---- cell state in registers: cell index = tid + it*NT -> (b, u) ----
    float c0r[4], c1r[4];
    #pragma unroll
    for (int it = 0; it < 4; it++) { c0r[it] = 0.0f; c1r[it] = 0.0f; }

    // zero h state
    for (int idx = tid; idx < BB * HID; idx += NT) {
        h0s[idx / HID][idx % HID] = 0.0f;
        h1s[idx / HID][idx % HID] = 0.0f;
    }
    // stage x(t=0)
    if (tid < nb * IN) {
        int b = tid / IN, j = tid % IN;
        xs[b][j] = x[(size_t)(b0 + b) * T_STEPS * IN + j];
    }
    __syncthreads();

    #pragma unroll 1
    for (int t = 0; t < T_STEPS; t++) {
        // ======== gate phase, layer 0 ========
        if (tid < G4) {
            for (int b = 0; b < nb; b++) {
                float a0 = bias0, a1 = 0.0f, a2 = 0.0f, a3 = 0.0f;
                #pragma unroll
                for (int j = 0; j < IN; j++) a0 += wx[j] * xs[b][j];
                const float4* hp = reinterpret_cast<const float4*>(h0s[b]);
                #pragma unroll
                for (int k4 = 0; k4 < HID / 4; k4++) {
                    float4 hv = hp[k4];
                    a0 += w0[4 * k4 + 0] * hv.x;
                    a1 += w0[4 * k4 + 1] * hv.y;
                    a2 += w0[4 * k4 + 2] * hv.z;
                    a3 += w0[4 * k4 + 3] * hv.w;
                }
                gsh[b][g] = (a0 + a1) + (a2 + a3);
            }
        }
        __syncthreads();

        // ======== cell phase, layer 0 ========
        #pragma unroll
        for (int it = 0; it < 4; it++) {
            int c = tid + it * NT;
            if (c < nb * HID) {
                int b = c / HID, u = c % HID;
                float gi = sigmoid_fast(gsh[b][u]);
                float gf = sigmoid_fast(gsh[b][HID + u]);
                float gg = tanh_fast(gsh[b][2 * HID + u]);
                float go = sigmoid_fast(gsh[b][3 * HID + u]);
                float cc = gf * c0r[it] + gi * gg;
                c0r[it] = cc;
                h0s[b][u] = go * tanh_fast(cc);
            }
        }
        __syncthreads();

        // ======== gate phase, layer 1 ========
        if (tid < G4) {
            for (int b = 0; b < nb; b++) {
                float a0 = bias1, a1 = 0.0f, a2 = 0.0f, a3 = 0.0f;
                const float4* hp0 = reinterpret_cast<const float4*>(h0s[b]);
                const float4* hp1 = reinterpret_cast<const float4*>(h1s[b]);
                #pragma unroll
                for (int k4 = 0; k4 < HID / 4; k4++) {
                    float4 av = hp0[k4];
                    a0 += wi1[4 * k4 + 0] * av.x;
                    a1 += wi1[4 * k4 + 1] * av.y;
                    a2 += wi1[4 * k4 + 2] * av.z;
                    a3 += wi1[4 * k4 + 3] * av.w;
                    float4 bv = hp1[k4];
                    a0 += w1[4 * k4 + 0] * bv.x;
                    a1 += w1[4 * k4 + 1] * bv.y;
                    a2 += w1[4 * k4 + 2] * bv.z;
                    a3 += w1[4 * k4 + 3] * bv.w;
                }
                gsh[b][g] = (a0 + a1) + (a2 + a3);
            }
        }
        __syncthreads();

        // ======== cell phase, layer 1  (+ stage x(t+1)) ========
        #pragma unroll
        for (int it = 0; it < 4; it++) {
            int c = tid + it * NT;
            if (c < nb * HID) {
                int b = c / HID, u = c % HID;
                float gi = sigmoid_fast(gsh[b][u]);
                float gf = sigmoid_fast(gsh[b][HID + u]);
                float gg = tanh_fast(gsh[b][2 * HID + u]);
                float go = sigmoid_fast(gsh[b][3 * HID + u]);
                float cc = gf * c1r[it] + gi * gg;
                c1r[it] = cc;
                h1s[b][u] = go * tanh_fast(cc);
            }
        }
        if (t + 1 < T_STEPS && tid < nb * IN) {
            int b = tid / IN, j = tid % IN;
            xs[b][j] = x[(size_t)(b0 + b) * T_STEPS * IN + (size_t)(t + 1) * IN + j];
        }
        __syncthreads();
    }

    // ======== FC head on final h1 ========
    if (tid < nb) {
        int b = tid;
        float acc2 = fc2_b[0];
        #pragma unroll 1
        for (int j = 0; j < HID / 2; j++) {
            float a = fc1_b[j];
            #pragma unroll
            for (int k = 0; k < HID; k++)
                a += fc1_w[j * HID + k] * h1s[b][k];
            a = fmaxf(a, 0.0f);
            acc2 += a * fc2_w[j];
        }
        out[b0 + b] = acc2;
    }
}

extern "C" void kernel_launch(void* const* d_in, const int* in_sizes, int n_in,
                              void* d_out, int out_size)
{
    const float* x     = (const float*)d_in[0];
    const float* w_ih0 = (const float*)d_in[1];
    const float* w_hh0 = (const float*)d_in[2];
    const float* b_ih0 = (const float*)d_in[3];
    const float* b_hh0 = (const float*)d_in[4];
    const float* w_ih1 = (const float*)d_in[5];
    const float* w_hh1 = (const float*)d_in[6];
    const float* b_ih1 = (const float*)d_in[7];
    const float* b_hh1 = (const float*)d_in[8];
    const float* fc1_w = (const float*)d_in[9];
    const float* fc1_b = (const float*)d_in[10];
    const float* fc2_w = (const float*)d_in[11];
    const float* fc2_b = (const float*)d_in[12];

    int B = out_size;                    // 2048 outputs, one per batch row
    int grid = (B + BB - 1) / BB;        // 147 CTAs

    lstm_fused_kernel<<<grid, NT>>>(x, w_ih0, w_hh0, b_ih0, b_hh0,
                                    w_ih1, w_hh1, b_ih1, b_hh1,
                                    fc1_w, fc1_b, fc2_w, fc2_b,
                                    (float*)d_out, B);
}

// round 3
// speedup vs baseline: 1.0879x; 1.0879x over previous
#include <cuda_runtime.h>

#define T_STEPS 512
#define IN      9
#define INP     10      // padded (even) x width
#define HID     56
#define G4      224     // 4*HID
#define BB      14      // batches per CTA
#define NT      256     // threads per CTA

typedef unsigned long long u64;

__device__ __forceinline__ u64 pack2(float lo, float hi) {
    u64 r;
    asm("mov.b64 %0, {%1, %2};" : "=l"(r) : "f"(lo), "f"(hi));
    return r;
}

__device__ __forceinline__ void fma2(u64& acc, u64 a, u64 b) {
    asm("fma.rn.f32x2 %0, %1, %2, %3;" : "=l"(acc) : "l"(a), "l"(b), "l"(acc));
}

__device__ __forceinline__ float hsum2(u64 a, u64 b) {
    u64 s;
    asm("add.rn.f32x2 %0, %1, %2;" : "=l"(s) : "l"(a), "l"(b));
    float lo, hi;
    asm("mov.b64 {%0, %1}, %2;" : "=f"(lo), "=f"(hi) : "l"(s));
    return lo + hi;
}

// overflow-safe fast tanh: exp argument always <= 0
__device__ __forceinline__ float tanh_fast(float v) {
    float e = __expf(-2.0f * fabsf(v));
    float t = __fdividef(1.0f - e, 1.0f + e);
    return copysignf(t, v);
}

__device__ __forceinline__ float sigmoid_fast(float v) {
    return __fdividef(1.0f, 1.0f + __expf(-v));
}

__global__ void __launch_bounds__(NT, 1)
lstm_fused_kernel(const float* __restrict__ x,
                  const float* __restrict__ w_ih0, const float* __restrict__ w_hh0,
                  const float* __restrict__ b_ih0, const float* __restrict__ b_hh0,
                  const float* __restrict__ w_ih1, const float* __restrict__ w_hh1,
                  const float* __restrict__ b_ih1, const float* __restrict__ b_hh1,
                  const float* __restrict__ fc1_w, const float* __restrict__ fc1_b,
                  const float* __restrict__ fc2_w, const float* __restrict__ fc2_b,
                  float* __restrict__ out, int batch_total)
{
    __shared__ __align__(16) float xs[BB][INP];     // padded, col 9 stays 0
    __shared__ __align__(16) float h0s[BB][HID];
    __shared__ __align__(16) float h1s[BB][HID];
    __shared__ float gsh[BB][G4];

    const int tid = threadIdx.x;
    const int b0  = blockIdx.x * BB;
    const int nb  = min(BB, batch_total - b0);   // uniform across block

    // ---- per-gate weights packed as f32x2 pairs in registers (threads 0..223) ----
    u64 wxp[INP / 2];          // 5
    u64 w0p[HID / 2];          // 28
    u64 wi1p[HID / 2];         // 28
    u64 w1p[HID / 2];          // 28
    u64 bias0p = 0, bias1p = 0;
    const int g = tid;
    if (tid < G4) {
        #pragma unroll
        for (int j = 0; j < IN / 2; j++)
            wxp[j] = pack2(w_ih0[g * IN + 2 * j], w_ih0[g * IN + 2 * j + 1]);
        wxp[4] = pack2(w_ih0[g * IN + 8], 0.0f);
        #pragma unroll
        for (int k = 0; k < HID / 2; k++) {
            w0p[k]  = pack2(w_hh0[g * HID + 2 * k], w_hh0[g * HID + 2 * k + 1]);
            wi1p[k] = pack2(w_ih1[g * HID + 2 * k], w_ih1[g * HID + 2 * k + 1]);
            w1p[k]  = pack2(w_hh1[g * HID + 2 * k], w_hh1[g * HID + 2 * k + 1]);
        }
        bias0p = pack2(b_ih0[g] + b_hh0[g], 0.0f);
        bias1p = pack2(b_ih1[g] + b_hh1[g], 0.0f);
    }

    // ---- cell state in registers: cell index = tid + it*NT -> (b, u) ----
    float c0r[4], c1r[4];
    #pragma unroll
    for (int it = 0; it < 4; it++) { c0r[it] = 0.0f; c1r[it] = 0.0f; }

    // zero h state + xs (incl. pad column)
    for (int idx = tid; idx < BB * HID; idx += NT) {
        h0s[idx / HID][idx % HID] = 0.0f;
        h1s[idx / HID][idx % HID] = 0.0f;
    }
    if (tid < BB * INP) xs[tid / INP][tid % INP] = 0.0f;
    __syncthreads();
    // stage x(t=0)
    if (tid < nb * IN) {
        int b = tid / IN, j = tid % IN;
        xs[b][j] = x[(size_t)(b0 + b) * T_STEPS * IN + j];
    }
    __syncthreads();

    #pragma unroll 1
    for (int t = 0; t < T_STEPS; t++) {
        // ======== gate phase, layer 0 ========
        if (tid < G4) {
            #pragma unroll 1
            for (int b = 0; b < nb; b++) {
                u64 acc0 = bias0p, acc1 = pack2(0.0f, 0.0f);
                const u64* xp = reinterpret_cast<const u64*>(xs[b]);
                #pragma unroll
                for (int j = 0; j < INP / 2; j++) fma2(acc0, wxp[j], xp[j]);
                const ulonglong2* hp = reinterpret_cast<const ulonglong2*>(h0s[b]);
                #pragma unroll
                for (int k = 0; k < HID / 4; k++) {
                    ulonglong2 hv = hp[k];
                    fma2(acc0, w0p[2 * k],     hv.x);
                    fma2(acc1, w0p[2 * k + 1], hv.y);
                }
                gsh[b][g] = hsum2(acc0, acc1);
            }
        }
        __syncthreads();

        // ======== cell phase, layer 0 ========
        #pragma unroll
        for (int it = 0; it < 4; it++) {
            int c = tid + it * NT;
            if (c < nb * HID) {
                int b = c / HID, u = c % HID;
                float gi = sigmoid_fast(gsh[b][u]);
                float gf = sigmoid_fast(gsh[b][HID + u]);
                float gg = tanh_fast(gsh[b][2 * HID + u]);
                float go = sigmoid_fast(gsh[b][3 * HID + u]);
                float cc = gf * c0r[it] + gi * gg;
                c0r[it] = cc;
                h0s[b][u] = go * tanh_fast(cc);
            }
        }
        __syncthreads();

        // ======== gate phase, layer 1 ========
        if (tid < G4) {
            #pragma unroll 1
            for (int b = 0; b < nb; b++) {
                u64 acc0 = bias1p, acc1 = pack2(0.0f, 0.0f);
                const ulonglong2* ap = reinterpret_cast<const ulonglong2*>(h0s[b]);
                const ulonglong2* bp = reinterpret_cast<const ulonglong2*>(h1s[b]);
                #pragma unroll
                for (int k = 0; k < HID / 4; k++) {
                    ulonglong2 av = ap[k];
                    fma2(acc0, wi1p[2 * k],     av.x);
                    fma2(acc1, wi1p[2 * k + 1], av.y);
                    ulonglong2 bv = bp[k];
                    fma2(acc0, w1p[2 * k],      bv.x);
                    fma2(acc1, w1p[2 * k + 1],  bv.y);
                }
                gsh[b][g] = hsum2(acc0, acc1);
            }
        }
        __syncthreads();

        // ======== cell phase, layer 1  (+ stage x(t+1)) ========
        #pragma unroll
        for (int it = 0; it < 4; it++) {
            int c = tid + it * NT;
            if (c < nb * HID) {
                int b = c / HID, u = c % HID;
                float gi = sigmoid_fast(gsh[b][u]);
                float gf = sigmoid_fast(gsh[b][HID + u]);
                float gg = tanh_fast(gsh[b][2 * HID + u]);
                float go = sigmoid_fast(gsh[b][3 * HID + u]);
                float cc = gf * c1r[it] + gi * gg;
                c1r[it] = cc;
                h1s[b][u] = go * tanh_fast(cc);
            }
        }
        if (t + 1 < T_STEPS && tid < nb * IN) {
            int b = tid / IN, j = tid % IN;
            xs[b][j] = x[(size_t)(b0 + b) * T_STEPS * IN + (size_t)(t + 1) * IN + j];
        }
        __syncthreads();
    }

    // ======== FC head on final h1 ========
    if (tid < nb) {
        int b = tid;
        float acc2 = fc2_b[0];
        #pragma unroll 1
        for (int j = 0; j < HID / 2; j++) {
            float a = fc1_b[j];
            #pragma unroll
            for (int k = 0; k < HID; k++)
                a += fc1_w[j * HID + k] * h1s[b][k];
            a = fmaxf(a, 0.0f);
            acc2 += a * fc2_w[j];
        }
        out[b0 + b] = acc2;
    }
}

extern "C" void kernel_launch(void* const* d_in, const int* in_sizes, int n_in,
                              void* d_out, int out_size)
{
    const float* x     = (const float*)d_in[0];
    const float* w_ih0 = (const float*)d_in[1];
    const float* w_hh0 = (const float*)d_in[2];
    const float* b_ih0 = (const float*)d_in[3];
    const float* b_hh0 = (const float*)d_in[4];
    const float* w_ih1 = (const float*)d_in[5];
    const float* w_hh1 = (const float*)d_in[6];
    const float* b_ih1 = (const float*)d_in[7];
    const float* b_hh1 = (const float*)d_in[8];
    const float* fc1_w = (const float*)d_in[9];
    const float* fc1_b = (const float*)d_in[10];
    const float* fc2_w = (const float*)d_in[11];
    const float* fc2_b = (const float*)d_in[12];

    int B = out_size;                    // 2048 outputs, one per batch row
    int grid = (B + BB - 1) / BB;        // 147 CTAs

    lstm_fused_kernel<<<grid, NT>>>(x, w_ih0, w_hh0, b_ih0, b_hh0,
                                    w_ih1, w_hh1, b_ih1, b_hh1,
                                    fc1_w, fc1_b, fc2_w, fc2_b,
                                    (float*)d_out, B);
}